// round 3
// baseline (speedup 1.0000x reference)
#include <cuda_runtime.h>
#include <cuda_bf16.h>

// CTC forward (keras ctc_batch_cost semantics) in scaled linear domain.
// B=128, T=512, C=1024 (blank = C-1), L=48, S = 2L+1 = 97.
//
// One warp per batch element; lane l owns states 4l..4l+3 in registers.
//   new[s] = (a[s] + a[s-1] + skip[s]*a[s-2]) * (p[t, ext[s]] + eps)
// Even (blank) states never skip, so the only cross-lane term per step is
// old a[4l-1] (one __shfl_up). Exact power-of-2 rescaling every 4 steps keeps
// alphas in range; accumulated exponent folded back as eTot*ln2 at the end.
//
// y_true dtype (int32 vs int64) is auto-detected on device: int64 labels
// viewed as int32 have all odd indices == 0.

#define BB 128
#define TT 512
#define CC 1024
#define LL 48
#define SS 97
#define EPSV 1e-7f
#define PD 16   // prefetch depth (register ring)

__device__ int g_lab_stride;  // 1 if labels are int32, 2 if int64 (int32-strided)

__global__ void detect_dtype_kernel(const int* __restrict__ yt32) {
    __shared__ int any_odd;
    if (threadIdx.x == 0) any_odd = 0;
    __syncthreads();
    int local = 0;
    // First BB*LL ints are in-bounds under both dtype hypotheses.
    for (int i = 1 + 2 * threadIdx.x; i < BB * LL; i += 2 * blockDim.x)
        local |= yt32[i];
    if (local) atomicOr(&any_odd, 1);
    __syncthreads();
    if (threadIdx.x == 0) g_lab_stride = any_odd ? 1 : 2;
}

__device__ __forceinline__ int load_label(const int* yt32, int idx, int stride) {
    int v = yt32[idx * stride];
    // clamp: insurance against misdetection (wrong answer, never a crash)
    return (v < 0) ? 0 : (v > CC - 1 ? CC - 1 : v);
}

__global__ __launch_bounds__(32, 1)
void ctc_fwd_kernel(const float* __restrict__ yp,
                    const int* __restrict__ yt32,
                    float* __restrict__ out) {
    const int b = blockIdx.x;
    const int lane = threadIdx.x;
    const unsigned FULL = 0xffffffffu;
    const int blank = CC - 1;
    const int stride = g_lab_stride;

    const float* __restrict__ P = yp + (size_t)b * (size_t)(TT * CC);
    const int* __restrict__ Yt = yt32 + (size_t)b * LL * stride;

    // labels owned by this lane: indices 2l and 2l+1 (odd states 4l+1, 4l+3)
    const int i0 = 2 * lane;
    const int i1 = 2 * lane + 1;
    const int lab0 = (i0 < LL) ? load_label(Yt, i0, stride) : blank;
    const int lab1 = (i1 < LL) ? load_label(Yt, i1, stride) : blank;
    const int labm1 = (i0 >= 1 && i0 <= LL) ? load_label(Yt, i0 - 1, stride) : -1;

    // skip-arc flags (state 1's nonexistent a[-1] handled by am1==0 at lane 0)
    const float sk1 = (lab0 != labm1) ? 1.0f : 0.0f;
    const float sk3 = (lab1 != lab0) ? 1.0f : 0.0f;

    // validity masks for states 4l+k < S
    const int s0 = 4 * lane;
    const float m0 = (s0 + 0 < SS) ? 1.0f : 0.0f;
    const float m1 = (s0 + 1 < SS) ? 1.0f : 0.0f;
    const float m2 = (s0 + 2 < SS) ? 1.0f : 0.0f;
    const float m3 = (s0 + 3 < SS) ? 1.0f : 0.0f;

    // t = 0 init
    float a0 = 0.0f, a1 = 0.0f, a2 = 0.0f, a3 = 0.0f;
    if (lane == 0) {
        a0 = P[blank] + EPSV;
        a1 = P[lab0] + EPSV;
    }

    // prefetch ring (blank + two labels per lane per timestep)
    float pb[PD], p0[PD], p1[PD];
#pragma unroll
    for (int i = 0; i < PD; i++) {
        const float* Pt = P + (size_t)(1 + i) * CC;
        pb[i] = Pt[blank];
        p0[i] = Pt[lab0];
        p1[i] = Pt[lab1];
    }

    int eTot = 0;

    for (int outer = 0; outer < 32; outer++) {
#pragma unroll
        for (int i = 0; i < PD; i++) {
            const int t = 1 + outer * PD + i;
            if (t < TT) {
                const float vb = pb[i] + EPSV;
                const float v0 = p0[i] + EPSV;
                const float v1 = p1[i] + EPSV;

                float am1 = __shfl_up_sync(FULL, a3, 1);
                if (lane == 0) am1 = 0.0f;

                const float n0 = (a0 + am1) * vb;             // even (blank)
                const float n1 = (a1 + a0 + sk1 * am1) * v0;  // odd
                const float n2 = (a2 + a1) * vb;              // even (blank)
                const float n3 = (a3 + a2 + sk3 * a1) * v1;   // odd

                a0 = n0 * m0;
                a1 = n1 * m1;
                a2 = n2 * m2;
                a3 = n3 * m3;

                const int tp = t + PD;
                if (tp < TT) {
                    const float* Pt = P + (size_t)tp * CC;
                    pb[i] = Pt[blank];
                    p0[i] = Pt[lab0];
                    p1[i] = Pt[lab1];
                }

                if ((i & 3) == 3) {
                    float m = fmaxf(fmaxf(a0, a1), fmaxf(a2, a3));
#pragma unroll
                    for (int off = 16; off; off >>= 1)
                        m = fmaxf(m, __shfl_xor_sync(FULL, m, off));
                    if (m > 0.0f) {
                        const int e = ((__float_as_int(m) >> 23) & 255) - 127;
                        const float sc = __int_as_float((127 - e) << 23);  // 2^-e
                        a0 *= sc; a1 *= sc; a2 *= sc; a3 *= sc;
                        eTot += e;
                    }
                }
            }
        }
    }

    // loss = -( log(alpha[S-1] + alpha[S-2]) + eTot*ln2 )
    const float aS1 = __shfl_sync(FULL, a0, 24);  // state 96 = lane 24 slot 0
    const float aS2 = __shfl_sync(FULL, a3, 23);  // state 95 = lane 23 slot 3
    if (lane == 0) {
        out[b] = -(logf(aS1 + aS2) + (float)eTot * 0.6931471805599453f);
    }
}

extern "C" void kernel_launch(void* const* d_in, const int* in_sizes, int n_in,
                              void* d_out, int out_size) {
    const float* yp;
    const int* yt32;
    // identify inputs by element count (y_pred: 128*512*1024, y_true: 128*48)
    if (in_sizes[0] == BB * LL) {
        yt32 = (const int*)d_in[0];
        yp = (const float*)d_in[1];
    } else {
        yp = (const float*)d_in[0];
        yt32 = (const int*)d_in[1];
    }
    detect_dtype_kernel<<<1, 256>>>(yt32);
    ctc_fwd_kernel<<<BB, 32>>>(yp, yt32, (float*)d_out);
}